// round 11
// baseline (speedup 1.0000x reference)
#include <cuda_runtime.h>

#define IMG     512
#define KW      33
#define HBLK    128
#define WBLK    128
#define PATCH_H 36
#define PATCH_W 160
#define PSTRIDE 168                      // words/patch row; 42x16B granules, 42 mod 8 == 2 -> conflict-free LDS.128
#define CSTRIDE (PATCH_H * PSTRIDE)      // 6048 words per channel
#define WBC     32                       // kernel-blocks per CTA (x)
#define NG      3                        // u-split groups
#define USTEP   11                       // u's per group (3*11 = 33)
#define KROW    36                       // padded v-stride (33 -> 36; 144B, 16B aligned)
#define KBUF_WORDS (NG * WBC * KROW)     // 3456 words per buffer
#define SMEM_WORDS (3 * CSTRIDE + 3 * KBUF_WORDS)
#define SMEM_BYTES (SMEM_WORDS * 4)      // 114,048 B -> 2 CTAs/SM (229.4KB of 233.5KB), 24 warps/SM

__device__ __forceinline__ unsigned smem_u32(const void* p) {
    unsigned a;
    asm("{ .reg .u64 t; cvta.to.shared.u64 t, %1; cvt.u32.u64 %0, t; }" : "=r"(a) : "l"(p));
    return a;
}

__global__ __launch_bounds__(384, 2)
void reblur_kernel(const float* __restrict__ img,
                   const float* __restrict__ Kg,
                   float* __restrict__ out)
{
    extern __shared__ float smem[];
    float* patchS = smem;                      // [3][36][PSTRIDE]
    float* KsmA   = smem + 3 * CSTRIDE;        // 3 rotating K buffers
    float* KsmB   = KsmA + KBUF_WORDS;
    float* KsmC   = KsmB + KBUF_WORDS;

    const int tid    = threadIdx.x;
    const int g      = tid >> 7;        // u-group 0..2 (also = channel for staging)
    const int wg_tid = tid & 127;
    const int oi     = wg_tid & 3;
    const int wbc    = wg_tid >> 2;     // 0..31
    const int warp   = tid >> 5;        // 0..11
    const int lane   = tid & 31;
    const int bx     = blockIdx.x;      // 0..3
    const int hb     = blockIdx.y;      // 0..127

    // -------- patch staging: divide-free, coalesced, cp.async (c = g) --------
    const int col0 = 128 * bx - 16;
    const int row0 = 4 * hb - 16;
    {
        const int  w     = wg_tid >> 5;                       // warp within group, 0..3
        const float* imgC = img + g * (IMG * IMG);
        unsigned   pbase = smem_u32(patchS + g * CSTRIDE);
        #pragma unroll
        for (int p = 0; p < 9; ++p) {
            int r  = w + 4 * p;
            int ri = min(max(row0 + r, 0), IMG - 1);          // 'edge' pad
            const float* srow = imgC + ri * IMG;
            unsigned drow = pbase + 4u * (unsigned)(r * PSTRIDE);
            #pragma unroll
            for (int q = 0; q < 5; ++q) {
                int x  = lane + 32 * q;
                int ci = min(max(col0 + x, 0), IMG - 1);
                asm volatile("cp.async.ca.shared.global [%0], [%1], 4;"
                             :: "r"(drow + 4u * (unsigned)x), "l"(srow + ci));
            }
        }
        asm volatile("cp.async.commit_group;" ::: "memory");
    }

    // ------- K staging: rows {t, t+11, t+22} -> [g][wb][v]; warp-structured, no div -------
    const float* Kbase = Kg + hb * WBLK + WBC * bx + lane;
    auto stage = [&](float* dstbuf, int t) {
        unsigned dbase = smem_u32(dstbuf) + 4u * (unsigned)(lane * KROW);
        int r = warp, g2 = 0, v = warp;     // warp < 12 < 33 so g2=0 initially
        #pragma unroll 1
        while (r < NG * KW) {               // 99 rows, 8-9 per warp
            int u = USTEP * g2 + t;
            const float* src = Kbase + (size_t)(u * KW + v) * (HBLK * WBLK);
            unsigned dst = dbase + 4u * (unsigned)(g2 * (WBC * KROW) + v);
            asm volatile("cp.async.ca.shared.global [%0], [%1], 4;" :: "r"(dst), "l"(src));
            r += 12; v += 12;
            if (v >= KW) { v -= KW; ++g2; }
        }
        asm volatile("cp.async.commit_group;" ::: "memory");
    };

    stage(KsmA, 0);     // K0
    stage(KsmB, 1);     // K1 — two steps of latency budget from here on

    // ---------------- main compute: 11 steps, v split in two halves ----------------
    float acc[3][4];
    #pragma unroll
    for (int c = 0; c < 3; ++c)
        #pragma unroll
        for (int j = 0; j < 4; ++j) acc[c][j] = 0.f;

    float* ka = KsmA;   // buffer holding K_t
    float* kb = KsmB;   // K_{t+1}
    float* kc = KsmC;   // target for K_{t+2}

    #pragma unroll 1
    for (int t = 0; t < USTEP; ++t) {
        // Drain K_t (leave at most 1 group — K_{t+1} — outstanding).
        if (t + 1 < USTEP) {
            asm volatile("cp.async.wait_group 1;" ::: "memory");
        } else {
            asm volatile("cp.async.wait_group 0;" ::: "memory");
        }
        __syncthreads();     // all threads see K_t; also fences compute(t-1) before stage below

        if (t + 2 < USTEP) stage(kc, t + 2);   // fully overlapped: not awaited until t+2

        const float* krow = ka + (g * WBC + wbc) * KROW;
        const float* prow = patchS + (oi + USTEP * g + t) * PSTRIDE + 4 * wbc;

        // ---- half 0: v in [0,16), uses p[0..18] ----
        {
            float kk[16];
            {
                const float4* ks = reinterpret_cast<const float4*>(krow);
                #pragma unroll
                for (int j = 0; j < 4; ++j) {
                    float4 v4 = ks[j];
                    kk[4*j] = v4.x; kk[4*j+1] = v4.y; kk[4*j+2] = v4.z; kk[4*j+3] = v4.w;
                }
            }
            #pragma unroll
            for (int c = 0; c < 3; ++c) {
                float p[20];
                const float4* ps = reinterpret_cast<const float4*>(prow + c * CSTRIDE);
                #pragma unroll
                for (int j = 0; j < 5; ++j) {
                    float4 v4 = ps[j];
                    p[4*j] = v4.x; p[4*j+1] = v4.y; p[4*j+2] = v4.z; p[4*j+3] = v4.w;
                }
                float a0 = acc[c][0], a1 = acc[c][1], a2 = acc[c][2], a3 = acc[c][3];
                #pragma unroll
                for (int v = 0; v < 16; ++v) {
                    float kv = kk[v];
                    a0 = fmaf(kv, p[v],     a0);
                    a1 = fmaf(kv, p[v + 1], a1);
                    a2 = fmaf(kv, p[v + 2], a2);
                    a3 = fmaf(kv, p[v + 3], a3);
                }
                acc[c][0] = a0; acc[c][1] = a1; acc[c][2] = a2; acc[c][3] = a3;
            }
        }

        // ---- half 1: v in [16,33), uses p[16..35] ----
        {
            float kk[20];                              // kk[17..19] = pads, unused
            {
                const float4* ks = reinterpret_cast<const float4*>(krow + 16);
                #pragma unroll
                for (int j = 0; j < 5; ++j) {
                    float4 v4 = ks[j];
                    kk[4*j] = v4.x; kk[4*j+1] = v4.y; kk[4*j+2] = v4.z; kk[4*j+3] = v4.w;
                }
            }
            #pragma unroll
            for (int c = 0; c < 3; ++c) {
                float p[20];
                const float4* ps = reinterpret_cast<const float4*>(prow + c * CSTRIDE + 16);
                #pragma unroll
                for (int j = 0; j < 5; ++j) {
                    float4 v4 = ps[j];
                    p[4*j] = v4.x; p[4*j+1] = v4.y; p[4*j+2] = v4.z; p[4*j+3] = v4.w;
                }
                float a0 = acc[c][0], a1 = acc[c][1], a2 = acc[c][2], a3 = acc[c][3];
                #pragma unroll
                for (int v = 0; v < 17; ++v) {
                    float kv = kk[v];
                    a0 = fmaf(kv, p[v],     a0);
                    a1 = fmaf(kv, p[v + 1], a1);
                    a2 = fmaf(kv, p[v + 2], a2);
                    a3 = fmaf(kv, p[v + 3], a3);
                }
                acc[c][0] = a0; acc[c][1] = a1; acc[c][2] = a2; acc[c][3] = a3;
            }
        }

        // rotate buffers: (ka,kb,kc) <- (kb,kc,ka)
        float* tmp = ka; ka = kb; kb = kc; kc = tmp;
    }

    // ---------------- 3-way reduction through smem (reuse patch region) ----------------
    float* red = patchS;   // 2*128*12 = 3072 words
    __syncthreads();       // everyone done reading patchS
    if (g > 0) {
        float* dst = red + ((g - 1) * 128 + wg_tid) * 12;
        #pragma unroll
        for (int c = 0; c < 3; ++c)
            #pragma unroll
            for (int j = 0; j < 4; ++j) dst[c * 4 + j] = acc[c][j];
    }
    __syncthreads();

    if (g == 0) {
        const float* p1 = red + wg_tid * 12;
        const float* p2 = red + (128 + wg_tid) * 12;
        const int orow = 4 * hb + oi;
        const int ocol = 128 * bx + 4 * wbc;
        #pragma unroll
        for (int c = 0; c < 3; ++c) {
            float4 r;
            r.x = acc[c][0] + p1[c*4+0] + p2[c*4+0];
            r.y = acc[c][1] + p1[c*4+1] + p2[c*4+1];
            r.z = acc[c][2] + p1[c*4+2] + p2[c*4+2];
            r.w = acc[c][3] + p1[c*4+3] + p2[c*4+3];
            *reinterpret_cast<float4*>(out + (c * IMG + orow) * IMG + ocol) = r;
        }
    }
}

extern "C" void kernel_launch(void* const* d_in, const int* in_sizes, int n_in,
                              void* d_out, int out_size)
{
    const float* img = (const float*)d_in[0];   // (1,3,512,512) fp32
    const float* Kg  = (const float*)d_in[1];   // (1,1089,128,128) fp32
    float* out = (float*)d_out;                 // (1,3,512,512) fp32

    cudaFuncSetAttribute(reblur_kernel,
                         cudaFuncAttributeMaxDynamicSharedMemorySize, SMEM_BYTES);
    dim3 grid(4, 128);
    reblur_kernel<<<grid, 384, SMEM_BYTES>>>(img, Kg, out);
}

// round 14
// speedup vs baseline: 1.3643x; 1.3643x over previous
#include <cuda_runtime.h>

#define IMG     512
#define KW      33
#define HBLK    128
#define WBLK    128
#define PATCH_H 36
#define PATCH_W 160
#define PSTRIDE 168                      // words/patch row; 42x16B granules, 42 mod 8 == 2 -> conflict-free LDS.128
#define CSTRIDE (PATCH_H * PSTRIDE)      // 6048 words per channel
#define WBC     32                       // kernel-blocks per CTA (x)
#define NG      3                        // u-split groups
#define USTEP   11                       // u's per group (3*11 = 33)
#define KROW    36                       // padded v-stride (33 -> 36); words 33..35 zeroed once
#define KBUF_WORDS (NG * WBC * KROW)     // 3456 words per buffer
#define SMEM_WORDS (3 * CSTRIDE + 2 * KBUF_WORDS)
#define SMEM_BYTES (SMEM_WORDS * 4)      // 100,224 B -> 2 CTAs/SM, 24 warps/SM, ~28KB L1 left

typedef unsigned long long u64;

__device__ __forceinline__ unsigned smem_u32(const void* p) {
    unsigned a;
    asm("{ .reg .u64 t; cvta.to.shared.u64 t, %1; cvt.u32.u64 %0, t; }" : "=r"(a) : "l"(p));
    return a;
}

__device__ __forceinline__ void fma2(u64& acc, u64 a, u64 b) {
    asm("fma.rn.f32x2 %0, %1, %2, %0;" : "+l"(acc) : "l"(a), "l"(b));
}

__global__ __launch_bounds__(384, 2)
void reblur_kernel(const float* __restrict__ img,
                   const float* __restrict__ Kg,
                   float* __restrict__ out)
{
    extern __shared__ float smem[];
    float* patchS = smem;                      // [3][36][PSTRIDE]
    float* Ksm0   = smem + 3 * CSTRIDE;        // [NG][WBC][KROW]
    float* Ksm1   = Ksm0 + KBUF_WORDS;

    const int tid    = threadIdx.x;
    const int g      = tid >> 7;        // u-group 0..2 (also = channel for staging)
    const int wg_tid = tid & 127;
    const int oi     = wg_tid & 3;
    const int wbc    = wg_tid >> 2;     // 0..31
    const int warp   = tid >> 5;        // 0..11
    const int lane   = tid & 31;
    const int bx     = blockIdx.x;      // 0..3
    const int hb     = blockIdx.y;      // 0..127

    // ---- zero K-row pads (v=33..35) of both buffers (cp.async never writes them) ----
    #pragma unroll 1
    for (int i = tid; i < 2 * NG * WBC * 3; i += 384) {          // 576 words
        int b   = i >= NG * WBC * 3;
        int r2  = b ? (i - NG * WBC * 3) : i;
        int row = r2 / 3;
        (b ? Ksm1 : Ksm0)[row * KROW + 33 + (r2 - row * 3)] = 0.f;
    }

    // -------- patch staging: divide-free, coalesced, cp.async (c = g) --------
    const int col0 = 128 * bx - 16;
    const int row0 = 4 * hb - 16;
    {
        const int  w     = wg_tid >> 5;                       // warp within group, 0..3
        const float* imgC = img + g * (IMG * IMG);
        unsigned   pbase = smem_u32(patchS + g * CSTRIDE);
        #pragma unroll
        for (int p = 0; p < 9; ++p) {
            int r  = w + 4 * p;
            int ri = min(max(row0 + r, 0), IMG - 1);          // 'edge' pad
            const float* srow = imgC + ri * IMG;
            unsigned drow = pbase + 4u * (unsigned)(r * PSTRIDE);
            #pragma unroll
            for (int q = 0; q < 5; ++q) {
                int x  = lane + 32 * q;
                int ci = min(max(col0 + x, 0), IMG - 1);
                asm volatile("cp.async.ca.shared.global [%0], [%1], 4;"
                             :: "r"(drow + 4u * (unsigned)x), "l"(srow + ci));
            }
        }
        asm volatile("cp.async.commit_group;" ::: "memory");
    }

    // ------- K staging: rows {t, t+11, t+22} -> [g][wb][v]; warp-structured, no div -------
    const float* Kbase = Kg + hb * WBLK + WBC * bx + lane;
    auto stage = [&](float* dstbuf, int t) {
        unsigned dbase = smem_u32(dstbuf) + 4u * (unsigned)(lane * KROW);
        int r = warp, g2 = 0, v = warp;     // warp < 12 < 33 so g2=0 initially
        #pragma unroll 1
        while (r < NG * KW) {               // 99 rows, 8-9 per warp
            int u = USTEP * g2 + t;
            const float* src = Kbase + (size_t)(u * KW + v) * (HBLK * WBLK);
            unsigned dst = dbase + 4u * (unsigned)(g2 * (WBC * KROW) + v);
            asm volatile("cp.async.ca.shared.global [%0], [%1], 4;" :: "r"(dst), "l"(src));
            r += 12; v += 12;
            if (v >= KW) { v -= KW; ++g2; }
        }
        asm volatile("cp.async.commit_group;" ::: "memory");
    };

    stage(Ksm0, 0);
    asm volatile("cp.async.wait_group 0;" ::: "memory");   // waits patch + K0
    __syncthreads();

    // ---------------- main compute: 11 steps, FFMA2 core, pair-tiles 6/6/5 ----------------
    // Packed accumulators per channel:
    //   A0 += KP[t]*P[t]   (even oj0)    A1 += KQ[t]*P[t]   (odd  oj1)
    //   A2 += KP[t]*P[t+1] (even oj2)    A3 += KQ[t]*P[t+1] (odd  oj3)
    // KP[t]=(k[2t],k[2t+1]) aligned from smem; KQ[t]=(k[2t-1],k[2t]) via funnel; P[t]=(p[2t],p[2t+1]).
    u64 A[3][4];
    #pragma unroll
    for (int c = 0; c < 3; ++c)
        #pragma unroll
        for (int j = 0; j < 4; ++j) A[c][j] = 0ull;

    #pragma unroll 1
    for (int t = 0; t < USTEP; ++t) {
        float* cur = (t & 1) ? Ksm1 : Ksm0;
        float* nxt = (t & 1) ? Ksm0 : Ksm1;
        if (t + 1 < USTEP) stage(nxt, t + 1);     // overlap next chunk's HBM loads

        const float* krow = cur + (g * WBC + wbc) * KROW;
        const float* prow = patchS + (oi + USTEP * g + t) * PSTRIDE + 4 * wbc;

        u64 kprev = 0ull;   // KP[-1]: hi lane (k[-1]) = 0
        #pragma unroll
        for (int T = 0; T < 3; ++T) {
            const int NP = (T < 2) ? 6 : 5;       // pairs this tile

            // KP: aligned 64-bit halves of LDS.128 (words 12T .. 12T+11)
            u64 KP[6];
            {
                const ulonglong2* ks = reinterpret_cast<const ulonglong2*>(krow + 12 * T);
                ulonglong2 k0 = ks[0], k1 = ks[1], k2 = ks[2];
                KP[0] = k0.x; KP[1] = k0.y; KP[2] = k1.x;
                KP[3] = k1.y; KP[4] = k2.x; KP[5] = k2.y;   // tile2: KP[5]=(k[34],k[35])=0, unused
            }
            // KQ: funnel of adjacent KP (only construction ALU in the loop)
            u64 KQ[6];
            KQ[0] = (kprev >> 32) | (KP[0] << 32);
            #pragma unroll
            for (int i = 1; i < 6; ++i) KQ[i] = (KP[i-1] >> 32) | (KP[i] << 32);
            kprev = KP[5];                        // carry (tile2's value never used)

            #pragma unroll
            for (int c = 0; c < 3; ++c) {
                // P[t] pairs: aligned LDS.128 at words 12T .. 12T+15 (tile2: +11)
                u64 P[7];
                {
                    const ulonglong2* ps = reinterpret_cast<const ulonglong2*>(
                        prow + c * CSTRIDE + 12 * T);
                    ulonglong2 p0 = ps[0], p1 = ps[1], p2 = ps[2];
                    P[0] = p0.x; P[1] = p0.y; P[2] = p1.x;
                    P[3] = p1.y; P[4] = p2.x; P[5] = p2.y;
                    if (T < 2) { ulonglong2 p3 = ps[3]; P[6] = p3.x; }
                    else       { P[6] = 0ull; }           // unused in tile2 (NP=5 -> max P[5])
                }
                u64 a0 = A[c][0], a1 = A[c][1], a2 = A[c][2], a3 = A[c][3];
                #pragma unroll
                for (int i = 0; i < 6; ++i) {
                    if (i < NP) {
                        fma2(a0, KP[i], P[i]);
                        fma2(a1, KQ[i], P[i]);
                        fma2(a2, KP[i], P[i + 1]);
                        fma2(a3, KQ[i], P[i + 1]);
                    }
                }
                A[c][0] = a0; A[c][1] = a1; A[c][2] = a2; A[c][3] = a3;
            }
        }

        asm volatile("cp.async.wait_group 0;" ::: "memory");
        __syncthreads();
    }

    // ---------------- unpack + 3-way reduction through smem ----------------
    float acc[3][4];
    #pragma unroll
    for (int c = 0; c < 3; ++c)
        #pragma unroll
        for (int j = 0; j < 4; ++j) {
            u64 x = A[c][j];
            acc[c][j] = __uint_as_float((unsigned)x) + __uint_as_float((unsigned)(x >> 32));
        }

    float* red = patchS;   // 2*128*12 = 3072 words
    __syncthreads();       // everyone done reading patchS
    if (g > 0) {
        float* dst = red + ((g - 1) * 128 + wg_tid) * 12;
        #pragma unroll
        for (int c = 0; c < 3; ++c)
            #pragma unroll
            for (int j = 0; j < 4; ++j) dst[c * 4 + j] = acc[c][j];
    }
    __syncthreads();

    if (g == 0) {
        const float* p1 = red + wg_tid * 12;
        const float* p2 = red + (128 + wg_tid) * 12;
        const int orow = 4 * hb + oi;
        const int ocol = 128 * bx + 4 * wbc;
        #pragma unroll
        for (int c = 0; c < 3; ++c) {
            float4 r;
            r.x = acc[c][0] + p1[c*4+0] + p2[c*4+0];
            r.y = acc[c][1] + p1[c*4+1] + p2[c*4+1];
            r.z = acc[c][2] + p1[c*4+2] + p2[c*4+2];
            r.w = acc[c][3] + p1[c*4+3] + p2[c*4+3];
            *reinterpret_cast<float4*>(out + (c * IMG + orow) * IMG + ocol) = r;
        }
    }
}

extern "C" void kernel_launch(void* const* d_in, const int* in_sizes, int n_in,
                              void* d_out, int out_size)
{
    const float* img = (const float*)d_in[0];   // (1,3,512,512) fp32
    const float* Kg  = (const float*)d_in[1];   // (1,1089,128,128) fp32
    float* out = (float*)d_out;                 // (1,3,512,512) fp32

    cudaFuncSetAttribute(reblur_kernel,
                         cudaFuncAttributeMaxDynamicSharedMemorySize, SMEM_BYTES);
    dim3 grid(4, 128);
    reblur_kernel<<<grid, 384, SMEM_BYTES>>>(img, Kg, out);
}

// round 15
// speedup vs baseline: 1.7344x; 1.2712x over previous
#include <cuda_runtime.h>

#define IMG     512
#define KW      33
#define HBLK    128
#define WBLK    128
#define PATCH_H 36
#define PATCH_W 160
#define PSTRIDE 168                      // words/patch row; 42x16B granules, 42 mod 8 == 2 -> conflict-free LDS.128
#define CSTRIDE (PATCH_H * PSTRIDE)      // 6048 words per channel
#define WBC     32                       // kernel-blocks per CTA (x)
#define NG      3                        // u-split groups
#define USTEP   11                       // u's per group (3*11 = 33)
#define KROW    36                       // padded v-stride (33 -> 36; 144B, 16B aligned)
#define KBUF_WORDS (NG * WBC * KROW)     // 3456 words per buffer
#define KSEG    (WBC * KROW)             // 1152 words per group segment
#define SMEM_WORDS (3 * CSTRIDE + 2 * KBUF_WORDS)
#define SMEM_BYTES (SMEM_WORDS * 4)      // 100,224 B -> 2 CTAs/SM, 24 warps/SM, ~28KB L1 left

__device__ __forceinline__ unsigned smem_u32(const void* p) {
    unsigned a;
    asm("{ .reg .u64 t; cvta.to.shared.u64 t, %1; cvt.u32.u64 %0, t; }" : "=r"(a) : "l"(p));
    return a;
}

__global__ __launch_bounds__(384, 2)
void reblur_kernel(const float* __restrict__ img,
                   const float* __restrict__ Kg,
                   float* __restrict__ out)
{
    extern __shared__ float smem[];
    float* patchS = smem;                      // [3][36][PSTRIDE]
    float* Ksm0   = smem + 3 * CSTRIDE;        // [NG][WBC][KROW]
    float* Ksm1   = Ksm0 + KBUF_WORDS;

    const int tid    = threadIdx.x;
    const int g      = tid >> 7;        // u-group 0..2 (4 warps each; also = channel for patch staging)
    const int wg_tid = tid & 127;
    const int oi     = wg_tid & 3;
    const int wbc    = wg_tid >> 2;     // 0..31
    const int lane   = tid & 31;
    const int bx     = blockIdx.x;      // 0..3
    const int hb     = blockIdx.y;      // 0..127

    // -------- patch staging: divide-free, coalesced, cp.async (channel = g) --------
    const int col0 = 128 * bx - 16;
    const int row0 = 4 * hb - 16;
    {
        const int  w     = wg_tid >> 5;                       // warp within group, 0..3
        const float* imgC = img + g * (IMG * IMG);
        unsigned   pbase = smem_u32(patchS + g * CSTRIDE);
        #pragma unroll
        for (int p = 0; p < 9; ++p) {
            int r  = w + 4 * p;
            int ri = min(max(row0 + r, 0), IMG - 1);          // 'edge' pad
            const float* srow = imgC + ri * IMG;
            unsigned drow = pbase + 4u * (unsigned)(r * PSTRIDE);
            #pragma unroll
            for (int q = 0; q < 5; ++q) {
                int x  = lane + 32 * q;
                int ci = min(max(col0 + x, 0), IMG - 1);
                asm volatile("cp.async.ca.shared.global [%0], [%1], 4;"
                             :: "r"(drow + 4u * (unsigned)x), "l"(srow + ci));
            }
        }
        asm volatile("cp.async.commit_group;" ::: "memory");
    }

    // ------- per-group K staging: group g stages ONLY row u = 11g + t into its segment -------
    // 1056 words (33 v x 32 wb) by 128 threads; v = idx>>5, wb = idx&31 (divide-free, coalesced)
    const float* Kpix = Kg + hb * WBLK + WBC * bx;     // + (u*KW+v)*HBLK*WBLK + wb
    const int ubase = USTEP * g;
    auto stageg = [&](float* dstbuf, int t) {
        const float* Ksrc = Kpix + (size_t)(ubase + t) * KW * (HBLK * WBLK);
        unsigned dbase = smem_u32(dstbuf) + 4u * (unsigned)(g * KSEG);
        #pragma unroll
        for (int j = 0; j < 9; ++j) {
            int idx = wg_tid + 128 * j;
            if (j < 8 || idx < KW * WBC) {             // last iter: only wg_tid < 32
                int v  = idx >> 5;
                int wb = idx & 31;
                const float* src = Ksrc + (size_t)v * (HBLK * WBLK) + wb;
                unsigned dst = dbase + 4u * (unsigned)(wb * KROW + v);
                asm volatile("cp.async.ca.shared.global [%0], [%1], 4;" :: "r"(dst), "l"(src));
            }
        }
        asm volatile("cp.async.commit_group;" ::: "memory");
    };

    stageg(Ksm0, 0);
    asm volatile("cp.async.wait_group 0;" ::: "memory");   // waits patch + own K0
    __syncthreads();                                        // global: patch written by all groups

    // ---------------- main compute: 11 steps, per-group sync only ----------------
    float acc[3][4];
    #pragma unroll
    for (int c = 0; c < 3; ++c)
        #pragma unroll
        for (int j = 0; j < 4; ++j) acc[c][j] = 0.f;

    const unsigned bar_id = (unsigned)(g + 1);   // named barriers 1..3, 128 threads each

    #pragma unroll 1
    for (int t = 0; t < USTEP; ++t) {
        float* cur = (t & 1) ? Ksm1 : Ksm0;
        float* nxt = (t & 1) ? Ksm0 : Ksm1;
        if (t + 1 < USTEP) stageg(nxt, t + 1);    // overlap next row's HBM loads

        const float* krow = cur + g * KSEG + wbc * KROW;
        const float* prow = patchS + (oi + ubase + t) * PSTRIDE + 4 * wbc;

        // ---- half 0: v in [0,16), uses p[0..18] ----
        {
            float kk[16];
            {
                const float4* ks = reinterpret_cast<const float4*>(krow);
                #pragma unroll
                for (int j = 0; j < 4; ++j) {
                    float4 v4 = ks[j];
                    kk[4*j] = v4.x; kk[4*j+1] = v4.y; kk[4*j+2] = v4.z; kk[4*j+3] = v4.w;
                }
            }
            #pragma unroll
            for (int c = 0; c < 3; ++c) {
                float p[20];
                const float4* ps = reinterpret_cast<const float4*>(prow + c * CSTRIDE);
                #pragma unroll
                for (int j = 0; j < 5; ++j) {
                    float4 v4 = ps[j];
                    p[4*j] = v4.x; p[4*j+1] = v4.y; p[4*j+2] = v4.z; p[4*j+3] = v4.w;
                }
                float a0 = acc[c][0], a1 = acc[c][1], a2 = acc[c][2], a3 = acc[c][3];
                #pragma unroll
                for (int v = 0; v < 16; ++v) {
                    float kv = kk[v];
                    a0 = fmaf(kv, p[v],     a0);
                    a1 = fmaf(kv, p[v + 1], a1);
                    a2 = fmaf(kv, p[v + 2], a2);
                    a3 = fmaf(kv, p[v + 3], a3);
                }
                acc[c][0] = a0; acc[c][1] = a1; acc[c][2] = a2; acc[c][3] = a3;
            }
        }

        // ---- half 1: v in [16,33), uses p[16..35] ----
        {
            float kk[20];                              // kk[17..19] = pads, unused
            {
                const float4* ks = reinterpret_cast<const float4*>(krow + 16);
                #pragma unroll
                for (int j = 0; j < 5; ++j) {
                    float4 v4 = ks[j];
                    kk[4*j] = v4.x; kk[4*j+1] = v4.y; kk[4*j+2] = v4.z; kk[4*j+3] = v4.w;
                }
            }
            #pragma unroll
            for (int c = 0; c < 3; ++c) {
                float p[20];
                const float4* ps = reinterpret_cast<const float4*>(prow + c * CSTRIDE + 16);
                #pragma unroll
                for (int j = 0; j < 5; ++j) {
                    float4 v4 = ps[j];
                    p[4*j] = v4.x; p[4*j+1] = v4.y; p[4*j+2] = v4.z; p[4*j+3] = v4.w;
                }
                float a0 = acc[c][0], a1 = acc[c][1], a2 = acc[c][2], a3 = acc[c][3];
                #pragma unroll
                for (int v = 0; v < 17; ++v) {
                    float kv = kk[v];
                    a0 = fmaf(kv, p[v],     a0);
                    a1 = fmaf(kv, p[v + 1], a1);
                    a2 = fmaf(kv, p[v + 2], a2);
                    a3 = fmaf(kv, p[v + 3], a3);
                }
                acc[c][0] = a0; acc[c][1] = a1; acc[c][2] = a2; acc[c][3] = a3;
            }
        }

        // Drain own K_{t+1}; sync ONLY this group's 4 warps (buffer segment is group-private).
        asm volatile("cp.async.wait_group 0;" ::: "memory");
        asm volatile("bar.sync %0, %1;" :: "r"(bar_id), "r"(128) : "memory");
    }

    // ---------------- 3-way reduction through smem (reuse patch region) ----------------
    float* red = patchS;   // 2*128*12 = 3072 words
    __syncthreads();       // global: everyone done reading patchS + all groups done
    if (g > 0) {
        float* dst = red + ((g - 1) * 128 + wg_tid) * 12;
        #pragma unroll
        for (int c = 0; c < 3; ++c)
            #pragma unroll
            for (int j = 0; j < 4; ++j) dst[c * 4 + j] = acc[c][j];
    }
    __syncthreads();

    if (g == 0) {
        const float* p1 = red + wg_tid * 12;
        const float* p2 = red + (128 + wg_tid) * 12;
        const int orow = 4 * hb + oi;
        const int ocol = 128 * bx + 4 * wbc;
        #pragma unroll
        for (int c = 0; c < 3; ++c) {
            float4 r;
            r.x = acc[c][0] + p1[c*4+0] + p2[c*4+0];
            r.y = acc[c][1] + p1[c*4+1] + p2[c*4+1];
            r.z = acc[c][2] + p1[c*4+2] + p2[c*4+2];
            r.w = acc[c][3] + p1[c*4+3] + p2[c*4+3];
            *reinterpret_cast<float4*>(out + (c * IMG + orow) * IMG + ocol) = r;
        }
    }
}

extern "C" void kernel_launch(void* const* d_in, const int* in_sizes, int n_in,
                              void* d_out, int out_size)
{
    const float* img = (const float*)d_in[0];   // (1,3,512,512) fp32
    const float* Kg  = (const float*)d_in[1];   // (1,1089,128,128) fp32
    float* out = (float*)d_out;                 // (1,3,512,512) fp32

    cudaFuncSetAttribute(reblur_kernel,
                         cudaFuncAttributeMaxDynamicSharedMemorySize, SMEM_BYTES);
    dim3 grid(4, 128);
    reblur_kernel<<<grid, 384, SMEM_BYTES>>>(img, Kg, out);
}